// round 15
// baseline (speedup 1.0000x reference)
#include <cuda_runtime.h>
#include <math.h>

#define N_NODES 8192
#define SEQ 256
#define H 32
#define NPB 16
#define NE 262144

typedef unsigned long long ull;

__device__ float g_h2[N_NODES * H];
__device__ float g_hW[N_NODES * H];
__device__ float g_agg[N_NODES * H];
__device__ float g_dinv[N_NODES];

__device__ __forceinline__ void ffma2(ull& d, ull a, ull b) {
    asm("fma.rn.f32x2 %0, %1, %2, %0;" : "+l"(d) : "l"(a), "l"(b));
}
__device__ __forceinline__ void fadd2(ull& d, ull a) {
    asm("add.rn.f32x2 %0, %0, %1;" : "+l"(d) : "l"(a));
}
__device__ __forceinline__ ull pack2(float lo, float hi) {
    ull r; asm("mov.b64 %0, {%1, %2};" : "=l"(r) : "f"(lo), "f"(hi)); return r;
}
__device__ __forceinline__ float2 unpack2(ull v) {
    float2 r; asm("mov.b64 {%0, %1}, %2;" : "=f"(r.x), "=f"(r.y) : "l"(v)); return r;
}
__device__ __forceinline__ float tanhap(float x) {
    float r; asm("tanh.approx.f32 %0, %1;" : "=f"(r) : "f"(x)); return r;
}

// dynamic smem layout (bytes)
#define OFF_WT 0
#define OFF_WH 16384
#define OFF_Z1 32768
#define OFF_Z2 40960
#define OFF_H1 49152
#define OFF_H2 51200
#define OFF_RM 53248
#define DYN_SMEM 53376

// =====================================================================
// Fused 2-layer LSTM, LN folded into LSTM2 matvec (r12 structure).
// 128 thr/block, 16 nodes/block -> grid 512 -> ONE wave at 4 blk/SM.
// Phase1: 2 passes x 8 nodes (same acc-reg footprint as r12).
// Phase2: 4 nodes per thread. 2 barriers/step, skewed schedule.
// =====================================================================
__global__ void __launch_bounds__(128, 4) lstm_kernel(
    const float* __restrict__ x,
    const float* __restrict__ Wih1, const float* __restrict__ Whh1,
    const float* __restrict__ bih1, const float* __restrict__ bhh1,
    const float* __restrict__ ln_g, const float* __restrict__ ln_b,
    const float* __restrict__ Wih2, const float* __restrict__ Whh2,
    const float* __restrict__ bih2, const float* __restrict__ bhh2)
{
    extern __shared__ __align__(16) char sm[];
    ulonglong2 (*wt2sh)[128] = (ulonglong2(*)[128])(sm + OFF_WT);
    ulonglong2 (*wh2sh)[128] = (ulonglong2(*)[128])(sm + OFF_WH);
    float (*z1s)[128] = (float(*)[128])(sm + OFF_Z1);
    float (*z2s)[128] = (float(*)[128])(sm + OFF_Z2);
    float (*h1s)[H]   = (float(*)[H])(sm + OFF_H1);
    float (*h2s)[H]   = (float(*)[H])(sm + OFF_H2);
    float2* rm        = (float2*)(sm + OFF_RM);

    const int tid  = threadIdx.x;
    const int j    = tid;
    const int base = blockIdx.x * NPB;

    // ---- Whh1 row -> regs; Wtil/Whh2 -> shared transposed-dense ----
    ull w1p[H / 2];
    float stil_j = 0.f, q_j = 0.f;
#pragma unroll
    for (int k2 = 0; k2 < H / 2; k2++) {
        int k = 2 * k2;
        float g0 = ln_g[k], g1 = ln_g[k + 1];
        float wa = Wih2[j * H + k], wb = Wih2[j * H + k + 1];
        w1p[k2] = pack2(Whh1[j * H + k], Whh1[j * H + k + 1]);
        ull wt = pack2(wa * g0, wb * g1);
        ull wh = pack2(Whh2[j * H + k], Whh2[j * H + k + 1]);
        if (k2 & 1) { wt2sh[k2 >> 1][j].y = wt; wh2sh[k2 >> 1][j].y = wh; }
        else        { wt2sh[k2 >> 1][j].x = wt; wh2sh[k2 >> 1][j].x = wh; }
        stil_j += wa * g0 + wb * g1;
        q_j    += wa * ln_b[k] + wb * ln_b[k + 1];
    }
    q_j += bih2[j] + bhh2[j];
    const float b1j = bih1[j] + bhh1[j];
    const float wx1 = Wih1[j];
    const int   gate = j >> 5;
    const float mS = (gate == 2) ? 1.0f : 0.5f;
    const float mA = (gate == 2) ? 1.0f : 0.5f;
    const float mB = (gate == 2) ? 0.0f : 0.5f;

    const int w = tid >> 5;         // phase2: nodes w, w+4, w+8, w+12
    const int u = tid & 31;
    float c1[4], c2[4];
#pragma unroll
    for (int n = 0; n < 4; n++) { c1[n] = 0.f; c2[n] = 0.f; }

    for (int i = tid; i < NPB * H; i += 128) {
        ((float*)h1s)[i] = 0.f;
        ((float*)h2s)[i] = 0.f;
    }
    __syncthreads();

    const float* xrow = x + base * SEQ;

    for (int t = 0; t <= SEQ; t++) {
        const int tx = (t < SEQ) ? t : SEQ - 1;
        // ===== Phase1: 2 passes x 8 nodes, k4-outer / node-inner =====
#pragma unroll
        for (int p = 0; p < 2; p++) {
            ull a1[8], a2[8], a3[8];
#pragma unroll
            for (int m8 = 0; m8 < 8; m8++) {
                float xv = __ldg(xrow + (8 * p + m8) * SEQ + tx);
                a1[m8] = pack2(fmaf(xv, wx1, b1j), 0.f);
                a2[m8] = 0ULL; a3[m8] = 0ULL;
            }
#pragma unroll
            for (int k4 = 0; k4 < H / 4; k4++) {
                ulonglong2 wt = wt2sh[k4][j];
                ulonglong2 wh = wh2sh[k4][j];
                ull w1a = w1p[2 * k4], w1b = w1p[2 * k4 + 1];
#pragma unroll
                for (int m8 = 0; m8 < 8; m8++) {
                    int m = 8 * p + m8;
                    ulonglong2 h1v = *(const ulonglong2*)&h1s[m][k4 * 4];
                    ulonglong2 h2v = *(const ulonglong2*)&h2s[m][k4 * 4];
                    ffma2(a1[m8], w1a,  h1v.x); ffma2(a1[m8], w1b,  h1v.y);
                    ffma2(a2[m8], wt.x, h1v.x); ffma2(a2[m8], wt.y, h1v.y);
                    ffma2(a3[m8], wh.x, h2v.x); ffma2(a3[m8], wh.y, h2v.y);
                }
            }
#pragma unroll
            for (int m8 = 0; m8 < 8; m8++) {
                int m = 8 * p + m8;
                float2 p1 = unpack2(a1[m8]);
                z1s[m][j] = fmaf(mA, tanhap(mS * (p1.x + p1.y)), mB);
                if (t) {
                    float2 p2 = unpack2(a2[m8]);
                    float2 p3 = unpack2(a3[m8]);
                    float2 rmm = rm[m];
                    float z2 = fmaf(rmm.x, p2.x + p2.y,
                                    fmaf(rmm.y, stil_j, q_j) + p3.x + p3.y);
                    z2s[m][j] = fmaf(mA, tanhap(mS * z2), mB);
                }
            }
        }
        __syncthreads();

        // ===== Phase2: 4 nodes per thread =====
        if (t) {   // cell2(t-1)
#pragma unroll
            for (int k = 0; k < 4; k++) {
                int n = 4 * k + w;
                float gi = z2s[n][u],         gf = z2s[n][H + u];
                float gg = z2s[n][2 * H + u], go = z2s[n][3 * H + u];
                c2[k] = fmaf(gf, c2[k], gi * gg);
                float h = go * tanhap(c2[k]);
                if (t < SEQ) h2s[n][u] = h;
                else         g_h2[(base + n) * H + u] = h;
            }
        }
        if (t < SEQ) {   // cell1(t) + LN stats
            ull sv[4];
            float hv[4];
#pragma unroll
            for (int k = 0; k < 4; k++) {
                int n = 4 * k + w;
                float gi = z1s[n][u],         gf = z1s[n][H + u];
                float gg = z1s[n][2 * H + u], go = z1s[n][3 * H + u];
                c1[k] = fmaf(gf, c1[k], gi * gg);
                hv[k] = go * tanhap(c1[k]);
                sv[k] = pack2(hv[k], hv[k] * hv[k]);
            }
#pragma unroll
            for (int off = 16; off; off >>= 1)
#pragma unroll
                for (int k = 0; k < 4; k++)
                    fadd2(sv[k], __shfl_xor_sync(0xffffffffu, sv[k], off));
#pragma unroll
            for (int k = 0; k < 4; k++) {
                int n = 4 * k + w;
                float2 s = unpack2(sv[k]);
                float mu = s.x * (1.0f / H);
                float ri = rsqrtf(fmaf(-mu, mu, s.y * (1.0f / H)) + 1e-5f);
                h1s[n][u] = hv[k];
                if (u == 0) rm[n] = make_float2(ri, -mu * ri);
            }
        }
        __syncthreads();
    }
}

// =====================================================================
// GCN stage (unchanged)
// =====================================================================
__global__ void dinv_init_kernel() {
    int i = blockIdx.x * blockDim.x + threadIdx.x;
    if (i < N_NODES) g_dinv[i] = 1.0f;
}
__global__ void deg_acc_kernel(const int* __restrict__ ei, const float* __restrict__ ew) {
    int e = blockIdx.x * blockDim.x + threadIdx.x;
    if (e < NE) atomicAdd(&g_dinv[ei[NE + e]], ew[e]);
}
__global__ void dinv_fin_kernel() {
    int i = blockIdx.x * blockDim.x + threadIdx.x;
    if (i < N_NODES) g_dinv[i] = rsqrtf(g_dinv[i]);
}

__global__ void gcn_pre_kernel(const float* __restrict__ inp, const float* __restrict__ Wg,
                               const float* __restrict__ bprev, int apply_elu)
{
    __shared__ float Ws[H * H];
    __shared__ float rows[8][H];
    int tid = threadIdx.x;
    int m = tid >> 5, u = tid & 31;
    int n = blockIdx.x * 8 + m;
    for (int i = tid; i < H * H; i += 256) Ws[i] = Wg[i];
    float v = inp[n * H + u];
    if (apply_elu) { v += bprev[u]; v = v > 0.f ? v : expm1f(v); }
    rows[m][u] = v;
    __syncthreads();
    float acc = 0.f;
#pragma unroll
    for (int k = 0; k < H; k++) acc = fmaf(rows[m][k], Ws[k * H + u], acc);
    float di = g_dinv[n];
    g_hW[n * H + u]  = acc;
    g_agg[n * H + u] = acc * di * di;
}

__global__ void gcn_scatter_kernel(const int* __restrict__ ei, const float* __restrict__ ew)
{
    int idx = blockIdx.x * blockDim.x + threadIdx.x;
    int e = idx >> 5, u = idx & 31;
    int s = ei[e];
    int d = ei[NE + e];
    float nrm = g_dinv[s] * ew[e] * g_dinv[d];
    atomicAdd(&g_agg[d * H + u], nrm * g_hW[s * H + u]);
}

__global__ void final_kernel(const float* __restrict__ bg2, const float* __restrict__ Wfc,
                             const float* __restrict__ bfc, float* __restrict__ out)
{
    int tid = threadIdx.x;
    int m = tid >> 5, u = tid & 31;
    int n = blockIdx.x * 8 + m;
    float g = g_agg[n * H + u] + bg2[u];
    g = g > 0.f ? g : expm1f(g);
    float s = g;
#pragma unroll
    for (int off = 16; off; off >>= 1) s += __shfl_xor_sync(0xffffffffu, s, off);
    float mean = s * (1.0f / H);
    float h2u = g_h2[n * H + u];
    float p0 = h2u * Wfc[u];
    float p1 = h2u * Wfc[33 + u];
#pragma unroll
    for (int off = 16; off; off >>= 1) {
        p0 += __shfl_xor_sync(0xffffffffu, p0, off);
        p1 += __shfl_xor_sync(0xffffffffu, p1, off);
    }
    if (u == 0) {
        float o0 = p0 + mean * Wfc[32]      + bfc[0];
        float o1 = p1 + mean * Wfc[33 + 32] + bfc[1];
        float mx = fmaxf(o0, o1);
        float lse = mx + logf(expf(o0 - mx) + expf(o1 - mx));
        out[n * 2 + 0] = o0 - lse;
        out[n * 2 + 1] = o1 - lse;
    }
}

// =====================================================================
extern "C" void kernel_launch(void* const* d_in, const int* in_sizes, int n_in,
                              void* d_out, int out_size)
{
    const float* x    = (const float*)d_in[0];
    const float* ew   = (const float*)d_in[1];
    const float* Wih1 = (const float*)d_in[2];
    const float* Whh1 = (const float*)d_in[3];
    const float* bih1 = (const float*)d_in[4];
    const float* bhh1 = (const float*)d_in[5];
    const float* lng  = (const float*)d_in[6];
    const float* lnb  = (const float*)d_in[7];
    const float* Wih2 = (const float*)d_in[8];
    const float* Whh2 = (const float*)d_in[9];
    const float* bih2 = (const float*)d_in[10];
    const float* bhh2 = (const float*)d_in[11];
    const float* Wg1  = (const float*)d_in[12];
    const float* bg1  = (const float*)d_in[13];
    const float* Wg2  = (const float*)d_in[14];
    const float* bg2  = (const float*)d_in[15];
    const float* Wfc  = (const float*)d_in[16];
    const float* bfc  = (const float*)d_in[17];
    const int*   eidx = (const int*)d_in[18];
    float* out = (float*)d_out;

    cudaFuncSetAttribute(lstm_kernel,
                         cudaFuncAttributeMaxDynamicSharedMemorySize, DYN_SMEM);

    // keep lstm_kernel as launch #4 for the fixed-skip ncu capture
    dinv_init_kernel<<<N_NODES / 256, 256>>>();
    deg_acc_kernel<<<NE / 256, 256>>>(eidx, ew);
    dinv_fin_kernel<<<N_NODES / 256, 256>>>();

    lstm_kernel<<<N_NODES / NPB, 128, DYN_SMEM>>>(
        x, Wih1, Whh1, bih1, bhh1, lng, lnb, Wih2, Whh2, bih2, bhh2);

    gcn_pre_kernel<<<N_NODES / 8, 256>>>(g_h2, Wg1, bg1, 0);
    gcn_scatter_kernel<<<(NE * 32) / 256, 256>>>(eidx, ew);

    gcn_pre_kernel<<<N_NODES / 8, 256>>>(g_agg, Wg2, bg1, 1);
    gcn_scatter_kernel<<<(NE * 32) / 256, 256>>>(eidx, ew);

    final_kernel<<<N_NODES / 8, 256>>>(bg2, Wfc, bfc, out);
}

// round 17
// speedup vs baseline: 1.1471x; 1.1471x over previous
#include <cuda_runtime.h>
#include <math.h>

#define N_NODES 8192
#define SEQ 256
#define H 32
#define G4 128
#define NPB 8
#define NE 262144

typedef unsigned long long ull;

__device__ float g_h2[N_NODES * H];
__device__ float g_hW[N_NODES * H];
__device__ float g_agg[N_NODES * H];
__device__ float g_dinv[N_NODES];

__device__ __forceinline__ void ffma2(ull& d, ull a, ull b) {
    asm("fma.rn.f32x2 %0, %1, %2, %0;" : "+l"(d) : "l"(a), "l"(b));
}
__device__ __forceinline__ void fadd2(ull& d, ull a) {
    asm("add.rn.f32x2 %0, %0, %1;" : "+l"(d) : "l"(a));
}
__device__ __forceinline__ ull pack2(float lo, float hi) {
    ull r; asm("mov.b64 %0, {%1, %2};" : "=l"(r) : "f"(lo), "f"(hi)); return r;
}
__device__ __forceinline__ float2 unpack2(ull v) {
    float2 r; asm("mov.b64 {%0, %1}, %2;" : "=f"(r.x), "=f"(r.y) : "l"(v)); return r;
}
__device__ __forceinline__ float tanhap(float x) {
    float r; asm("tanh.approx.f32 %0, %1;" : "=f"(r) : "f"(x)); return r;
}

// =====================================================================
// Fused 2-layer LSTM, LN folded into the LSTM2 input matvec (champion
// r11 structure): both Phase1 matvecs read h1 (one shared load feeds
// Whh1-row and Wtil-row streams) + h2. Thread j owns z-row j. 8 nodes
// per block, 3 blocks/SM, 2 barriers/step, skewed schedule.
// t=0 peeled; merged h1/h2 k4 loop; x via __ldg (L1-cached).
// =====================================================================
__global__ void __launch_bounds__(128, 3) lstm_kernel(
    const float* __restrict__ x,
    const float* __restrict__ Wih1, const float* __restrict__ Whh1,
    const float* __restrict__ bih1, const float* __restrict__ bhh1,
    const float* __restrict__ ln_g, const float* __restrict__ ln_b,
    const float* __restrict__ Wih2, const float* __restrict__ Whh2,
    const float* __restrict__ bih2, const float* __restrict__ bhh2)
{
    __shared__ __align__(16) float h1s[NPB][H];
    __shared__ __align__(16) float h2s[NPB][H];
    __shared__ __align__(16) float z1s[NPB][G4];
    __shared__ __align__(16) float z2s[NPB][G4];
    __shared__ float2 rm[NPB];                 // (rinv, -mu*rinv) per node

    const int tid  = threadIdx.x;
    const int j    = tid;
    const int base = blockIdx.x * NPB;

    // ---- per-row weights -> registers (packed pairs) ----
    ull w1p[H / 2], wt2p[H / 2], wh2p[H / 2];
    float stil_j = 0.f, q_j = 0.f;
#pragma unroll
    for (int k2 = 0; k2 < H / 2; k2++) {
        int k = 2 * k2;
        float g0 = ln_g[k], g1 = ln_g[k + 1];
        float wa = Wih2[j * H + k], wb = Wih2[j * H + k + 1];
        w1p[k2]  = pack2(Whh1[j * H + k], Whh1[j * H + k + 1]);
        wt2p[k2] = pack2(wa * g0, wb * g1);
        wh2p[k2] = pack2(Whh2[j * H + k], Whh2[j * H + k + 1]);
        stil_j += wa * g0 + wb * g1;
        q_j    += wa * ln_b[k] + wb * ln_b[k + 1];
    }
    q_j += bih2[j] + bhh2[j];
    const float b1j = bih1[j] + bhh1[j];
    const float wx1 = Wih1[j];
    const int   gate = j >> 5;                 // uniform per warp
    const float mS = (gate == 2) ? 1.0f : 0.5f;
    const float mA = (gate == 2) ? 1.0f : 0.5f;
    const float mB = (gate == 2) ? 0.0f : 0.5f;

    const int mA0 = tid >> 5;
    const int mA1 = mA0 + 4;
    const int u   = tid & 31;
    float c1a = 0.f, c2a = 0.f, c1b = 0.f, c2b = 0.f;

    h1s[mA0][u] = 0.f; h1s[mA1][u] = 0.f;
    h2s[mA0][u] = 0.f; h2s[mA1][u] = 0.f;
    __syncthreads();

    const float* xrow = x + base * SEQ;

    // =========== peeled t = 0: matvec1 only (h1 = 0 -> z1 = act(x*w+b)) ===========
    {
#pragma unroll
        for (int m = 0; m < NPB; m++) {
            float z = fmaf(__ldg(xrow + m * SEQ), wx1, b1j);
            z1s[m][j] = fmaf(mA, tanhap(mS * z), mB);
        }
    }
    __syncthreads();
    {   // cell1(0) + LN
        float gia = z1s[mA0][u], gfa = z1s[mA0][H + u];
        float gga = z1s[mA0][2 * H + u], goa = z1s[mA0][3 * H + u];
        float gib = z1s[mA1][u], gfb = z1s[mA1][H + u];
        float ggb = z1s[mA1][2 * H + u], gob = z1s[mA1][3 * H + u];
        c1a = gia * gga;                       // f*0 + i*g
        c1b = gib * ggb;
        float hA = goa * tanhap(c1a);
        float hB = gob * tanhap(c1b);
        ull svA = pack2(hA, hA * hA);
        ull svB = pack2(hB, hB * hB);
#pragma unroll
        for (int off = 16; off; off >>= 1) {
            fadd2(svA, __shfl_xor_sync(0xffffffffu, svA, off));
            fadd2(svB, __shfl_xor_sync(0xffffffffu, svB, off));
        }
        float2 sA = unpack2(svA), sB = unpack2(svB);
        float muA = sA.x * (1.0f / H);
        float muB = sB.x * (1.0f / H);
        float riA = rsqrtf(fmaf(-muA, muA, sA.y * (1.0f / H)) + 1e-5f);
        float riB = rsqrtf(fmaf(-muB, muB, sB.y * (1.0f / H)) + 1e-5f);
        h1s[mA0][u] = hA;
        h1s[mA1][u] = hB;
        if (u == 0) {
            rm[mA0] = make_float2(riA, -muA * riA);
            rm[mA1] = make_float2(riB, -muB * riB);
        }
    }
    __syncthreads();

    // =========== steady state: t = 1 .. SEQ-1 (branch-free body) ===========
    for (int t = 1; t < SEQ; t++) {
        // ---- Phase1: z1(t) + z2(t-1), merged k4 loop per node ----
#pragma unroll
        for (int m = 0; m < NPB; m++) {
            ull a1 = pack2(fmaf(__ldg(xrow + m * SEQ + t), wx1, b1j), 0.f);
            ull a2 = 0ULL, a3 = 0ULL;
#pragma unroll
            for (int k4 = 0; k4 < H / 4; k4++) {
                ulonglong2 h1v = *(const ulonglong2*)&h1s[m][k4 * 4];
                ulonglong2 h2v = *(const ulonglong2*)&h2s[m][k4 * 4];
                ffma2(a1, w1p[2 * k4],      h1v.x);
                ffma2(a1, w1p[2 * k4 + 1],  h1v.y);
                ffma2(a2, wt2p[2 * k4],     h1v.x);
                ffma2(a2, wt2p[2 * k4 + 1], h1v.y);
                ffma2(a3, wh2p[2 * k4],     h2v.x);
                ffma2(a3, wh2p[2 * k4 + 1], h2v.y);
            }
            float2 p1 = unpack2(a1);
            z1s[m][j] = fmaf(mA, tanhap(mS * (p1.x + p1.y)), mB);
            float2 p2 = unpack2(a2);
            float2 p3 = unpack2(a3);
            float2 rmm = rm[m];
            float z2 = fmaf(rmm.x, p2.x + p2.y,
                            fmaf(rmm.y, stil_j, q_j) + p3.x + p3.y);
            z2s[m][j] = fmaf(mA, tanhap(mS * z2), mB);
        }
        __syncthreads();

        // ---- Phase2: cell2(t-1) ----
        {
            float gia = z2s[mA0][u], gfa = z2s[mA0][H + u];
            float gga = z2s[mA0][2 * H + u], goa = z2s[mA0][3 * H + u];
            float gib = z2s[mA1][u], gfb = z2s[mA1][H + u];
            float ggb = z2s[mA1][2 * H + u], gob = z2s[mA1][3 * H + u];
            c2a = fmaf(gfa, c2a, gia * gga);
            c2b = fmaf(gfb, c2b, gib * ggb);
            h2s[mA0][u] = goa * tanhap(c2a);
            h2s[mA1][u] = gob * tanhap(c2b);
        }
        // ---- Phase2: cell1(t) + LN stats ----
        {
            float gia = z1s[mA0][u], gfa = z1s[mA0][H + u];
            float gga = z1s[mA0][2 * H + u], goa = z1s[mA0][3 * H + u];
            float gib = z1s[mA1][u], gfb = z1s[mA1][H + u];
            float ggb = z1s[mA1][2 * H + u], gob = z1s[mA1][3 * H + u];
            c1a = fmaf(gfa, c1a, gia * gga);
            c1b = fmaf(gfb, c1b, gib * ggb);
            float hA = goa * tanhap(c1a);
            float hB = gob * tanhap(c1b);

            ull svA = pack2(hA, hA * hA);
            ull svB = pack2(hB, hB * hB);
#pragma unroll
            for (int off = 16; off; off >>= 1) {
                fadd2(svA, __shfl_xor_sync(0xffffffffu, svA, off));
                fadd2(svB, __shfl_xor_sync(0xffffffffu, svB, off));
            }
            float2 sA = unpack2(svA), sB = unpack2(svB);
            float muA = sA.x * (1.0f / H);
            float muB = sB.x * (1.0f / H);
            float riA = rsqrtf(fmaf(-muA, muA, sA.y * (1.0f / H)) + 1e-5f);
            float riB = rsqrtf(fmaf(-muB, muB, sB.y * (1.0f / H)) + 1e-5f);
            h1s[mA0][u] = hA;
            h1s[mA1][u] = hB;
            if (u == 0) {
                rm[mA0] = make_float2(riA, -muA * riA);
                rm[mA1] = make_float2(riB, -muB * riB);
            }
        }
        __syncthreads();
    }

    // =========== peeled tail: z2(SEQ-1) + final cell2 -> g_h2 ===========
    {
#pragma unroll
        for (int m = 0; m < NPB; m++) {
            ull a2 = 0ULL, a3 = 0ULL;
#pragma unroll
            for (int k4 = 0; k4 < H / 4; k4++) {
                ulonglong2 h1v = *(const ulonglong2*)&h1s[m][k4 * 4];
                ulonglong2 h2v = *(const ulonglong2*)&h2s[m][k4 * 4];
                ffma2(a2, wt2p[2 * k4],     h1v.x);
                ffma2(a2, wt2p[2 * k4 + 1], h1v.y);
                ffma2(a3, wh2p[2 * k4],     h2v.x);
                ffma2(a3, wh2p[2 * k4 + 1], h2v.y);
            }
            float2 p2 = unpack2(a2);
            float2 p3 = unpack2(a3);
            float2 rmm = rm[m];
            float z2 = fmaf(rmm.x, p2.x + p2.y,
                            fmaf(rmm.y, stil_j, q_j) + p3.x + p3.y);
            z2s[m][j] = fmaf(mA, tanhap(mS * z2), mB);
        }
    }
    __syncthreads();
    {
        float gia = z2s[mA0][u], gfa = z2s[mA0][H + u];
        float gga = z2s[mA0][2 * H + u], goa = z2s[mA0][3 * H + u];
        float gib = z2s[mA1][u], gfb = z2s[mA1][H + u];
        float ggb = z2s[mA1][2 * H + u], gob = z2s[mA1][3 * H + u];
        c2a = fmaf(gfa, c2a, gia * gga);
        c2b = fmaf(gfb, c2b, gib * ggb);
        g_h2[(base + mA0) * H + u] = goa * tanhap(c2a);
        g_h2[(base + mA1) * H + u] = gob * tanhap(c2b);
    }
}

// =====================================================================
// GCN stage (unchanged)
// =====================================================================
__global__ void dinv_init_kernel() {
    int i = blockIdx.x * blockDim.x + threadIdx.x;
    if (i < N_NODES) g_dinv[i] = 1.0f;
}
__global__ void deg_acc_kernel(const int* __restrict__ ei, const float* __restrict__ ew) {
    int e = blockIdx.x * blockDim.x + threadIdx.x;
    if (e < NE) atomicAdd(&g_dinv[ei[NE + e]], ew[e]);
}
__global__ void dinv_fin_kernel() {
    int i = blockIdx.x * blockDim.x + threadIdx.x;
    if (i < N_NODES) g_dinv[i] = rsqrtf(g_dinv[i]);
}

__global__ void gcn_pre_kernel(const float* __restrict__ inp, const float* __restrict__ Wg,
                               const float* __restrict__ bprev, int apply_elu)
{
    __shared__ float Ws[H * H];
    __shared__ float rows[8][H];
    int tid = threadIdx.x;
    int m = tid >> 5, u = tid & 31;
    int n = blockIdx.x * 8 + m;
    for (int i = tid; i < H * H; i += 256) Ws[i] = Wg[i];
    float v = inp[n * H + u];
    if (apply_elu) { v += bprev[u]; v = v > 0.f ? v : expm1f(v); }
    rows[m][u] = v;
    __syncthreads();
    float acc = 0.f;
#pragma unroll
    for (int k = 0; k < H; k++) acc = fmaf(rows[m][k], Ws[k * H + u], acc);
    float di = g_dinv[n];
    g_hW[n * H + u]  = acc;
    g_agg[n * H + u] = acc * di * di;
}

__global__ void gcn_scatter_kernel(const int* __restrict__ ei, const float* __restrict__ ew)
{
    int idx = blockIdx.x * blockDim.x + threadIdx.x;
    int e = idx >> 5, u = idx & 31;
    int s = ei[e];
    int d = ei[NE + e];
    float nrm = g_dinv[s] * ew[e] * g_dinv[d];
    atomicAdd(&g_agg[d * H + u], nrm * g_hW[s * H + u]);
}

__global__ void final_kernel(const float* __restrict__ bg2, const float* __restrict__ Wfc,
                             const float* __restrict__ bfc, float* __restrict__ out)
{
    int tid = threadIdx.x;
    int m = tid >> 5, u = tid & 31;
    int n = blockIdx.x * 8 + m;
    float g = g_agg[n * H + u] + bg2[u];
    g = g > 0.f ? g : expm1f(g);
    float s = g;
#pragma unroll
    for (int off = 16; off; off >>= 1) s += __shfl_xor_sync(0xffffffffu, s, off);
    float mean = s * (1.0f / H);
    float h2u = g_h2[n * H + u];
    float p0 = h2u * Wfc[u];
    float p1 = h2u * Wfc[33 + u];
#pragma unroll
    for (int off = 16; off; off >>= 1) {
        p0 += __shfl_xor_sync(0xffffffffu, p0, off);
        p1 += __shfl_xor_sync(0xffffffffu, p1, off);
    }
    if (u == 0) {
        float o0 = p0 + mean * Wfc[32]      + bfc[0];
        float o1 = p1 + mean * Wfc[33 + 32] + bfc[1];
        float mx = fmaxf(o0, o1);
        float lse = mx + logf(expf(o0 - mx) + expf(o1 - mx));
        out[n * 2 + 0] = o0 - lse;
        out[n * 2 + 1] = o1 - lse;
    }
}

// =====================================================================
extern "C" void kernel_launch(void* const* d_in, const int* in_sizes, int n_in,
                              void* d_out, int out_size)
{
    const float* x    = (const float*)d_in[0];
    const float* ew   = (const float*)d_in[1];
    const float* Wih1 = (const float*)d_in[2];
    const float* Whh1 = (const float*)d_in[3];
    const float* bih1 = (const float*)d_in[4];
    const float* bhh1 = (const float*)d_in[5];
    const float* lng  = (const float*)d_in[6];
    const float* lnb  = (const float*)d_in[7];
    const float* Wih2 = (const float*)d_in[8];
    const float* Whh2 = (const float*)d_in[9];
    const float* bih2 = (const float*)d_in[10];
    const float* bhh2 = (const float*)d_in[11];
    const float* Wg1  = (const float*)d_in[12];
    const float* bg1  = (const float*)d_in[13];
    const float* Wg2  = (const float*)d_in[14];
    const float* bg2  = (const float*)d_in[15];
    const float* Wfc  = (const float*)d_in[16];
    const float* bfc  = (const float*)d_in[17];
    const int*   eidx = (const int*)d_in[18];
    float* out = (float*)d_out;

    // keep lstm_kernel as launch #4 for the fixed-skip ncu capture
    dinv_init_kernel<<<N_NODES / 256, 256>>>();
    deg_acc_kernel<<<NE / 256, 256>>>(eidx, ew);
    dinv_fin_kernel<<<N_NODES / 256, 256>>>();

    lstm_kernel<<<N_NODES / NPB, 128>>>(x, Wih1, Whh1, bih1, bhh1, lng, lnb,
                                        Wih2, Whh2, bih2, bhh2);

    gcn_pre_kernel<<<N_NODES / 8, 256>>>(g_h2, Wg1, bg1, 0);
    gcn_scatter_kernel<<<(NE * 32) / 256, 256>>>(eidx, ew);

    gcn_pre_kernel<<<N_NODES / 8, 256>>>(g_agg, Wg2, bg1, 1);
    gcn_scatter_kernel<<<(NE * 32) / 256, 256>>>(eidx, ew);

    final_kernel<<<N_NODES / 8, 256>>>(bg2, Wfc, bfc, out);
}